// round 6
// baseline (speedup 1.0000x reference)
#include <cuda_runtime.h>
#include <cuda_fp16.h>
#include <cstdint>

// ============================================================================
// Problem constants — fp16 MMA, fp16 A staged via LDG->cvt->STS, K pad 784->800
// ============================================================================
#define KDIM      784
#define KPAD      800
#define KCH       32          // K per pipeline chunk
#define NCHUNK    25          // KPAD / KCH
#define MT        128
#define NT        128
#define NSTAGES   4
#define THREADS   256         // 8 warps: 4 in M x 2 in N, warp tile M32xN64

// Both tiles fp16, pitch 40 halves (80 B/row).
// ldmatrix (A): 8 rows at 80 B stride -> 16B-super-bank permutation, conflict-free.
// B b32 loads: banks 20*tg+tk cover all 32, conflict-free.
#define APITCH    40                       // halves
#define BPITCH    40                       // halves
#define A_BYTES   (MT * APITCH * 2)        // 10240
#define B_BYTES   (NT * BPITCH * 2)        // 10240
#define STAGE_BYTES (A_BYTES + B_BYTES)    // 20480
#define PH        130                      // h staging pitch (floats)

// smem float offsets
#define OF_PIPE   0                        // 4*20480 B = 81920 B (20480 floats)
#define OF_W2     20480                    // 1280
#define OF_B1     21760                    // 128
#define OF_B2     21888                    // 16 (10 used)
#define SMEM_FLOATS 21904
#define SMEM_BYTES  (SMEM_FLOATS * 4)      // 87616 -> 2 CTAs/SM
// epilogue overlays (pipeline dead): h[128][130] = 16640 floats
#define OF_PART   16640                    // 256*10
#define OF_OUTS   19200                    // 1280

// W_eff transposed, fp16-RN: g_Wt16[n*KPAD + k] = fp16(W_eff[k][n]), 0 for k>=784
__device__ __align__(16) __half g_Wt16[NT * KPAD];

// ============================================================================
// helpers (baseline PTX only — no 'a'-suffix features survive compute_103)
// ============================================================================
__device__ __forceinline__ uint32_t smem_u32(const void* p) {
    uint32_t a;
    asm("{ .reg .u64 t; cvta.to.shared.u64 t, %1; cvt.u32.u64 %0, t; }" : "=r"(a) : "l"(p));
    return a;
}
__device__ __forceinline__ uint32_t pack_f16x2(float lo, float hi) {
    uint32_t r;
    asm("cvt.rn.f16x2.f32 %0, %2, %1;" : "=r"(r) : "f"(lo), "f"(hi));
    return r;
}
__device__ __forceinline__ void cp_async16(uint32_t dst_smem, const void* src) {
    asm volatile("cp.async.cg.shared.global [%0], [%1], 16;" :: "r"(dst_smem), "l"(src) : "memory");
}
__device__ __forceinline__ void cp_commit() { asm volatile("cp.async.commit_group;" ::: "memory"); }
__device__ __forceinline__ void cp_wait2()  { asm volatile("cp.async.wait_group 2;" ::: "memory"); }
__device__ __forceinline__ void cp_wait0()  { asm volatile("cp.async.wait_group 0;" ::: "memory"); }

__device__ __forceinline__ void ldmatrix_x4(uint32_t* r, uint32_t addr) {
    asm volatile("ldmatrix.sync.aligned.m8n8.x4.shared.b16 {%0,%1,%2,%3}, [%4];"
                 : "=r"(r[0]), "=r"(r[1]), "=r"(r[2]), "=r"(r[3]) : "r"(addr));
}
__device__ __forceinline__ void mma_f16(float* c, const uint32_t* a, const uint32_t* b) {
    asm volatile("mma.sync.aligned.m16n8k16.row.col.f32.f16.f16.f32 "
                 "{%0,%1,%2,%3}, {%4,%5,%6,%7}, {%8,%9}, {%0,%1,%2,%3};"
                 : "+f"(c[0]), "+f"(c[1]), "+f"(c[2]), "+f"(c[3])
                 : "r"(a[0]), "r"(a[1]), "r"(a[2]), "r"(a[3]), "r"(b[0]), "r"(b[1]));
}

// ============================================================================
// Prep kernel: W_eff^T = (conv ⊗ w1), fp16-RN
// ============================================================================
__global__ void prep_kernel(const float* __restrict__ conv_w, const float* __restrict__ w1) {
    int idx = blockIdx.x * blockDim.x + threadIdx.x;
    if (idx >= NT * KPAD) return;
    int n = idx / KPAD;
    int k = idx - n * KPAD;
    float v = 0.f;
    if (k < KDIM) {
        int i = k / 28, j = k - (k / 28) * 28;
        #pragma unroll
        for (int dy = 0; dy < 3; ++dy) {
            int r = i - dy;
            if (r < 0 || r >= 26) continue;
            #pragma unroll
            for (int dx = 0; dx < 3; ++dx) {
                int c = j - dx;
                if (c < 0 || c >= 26) continue;
                v += conv_w[dy * 3 + dx] * w1[(r * 26 + c) * 128 + n];
            }
        }
    }
    g_Wt16[idx] = __float2half_rn(v);
}

// ============================================================================
// Main fused kernel: out = relu(x @ W_eff + b1) @ w2 + b2
// ============================================================================
__global__ void __launch_bounds__(THREADS, 2)
fused_mlp_kernel(const float* __restrict__ x, const float* __restrict__ b1,
                 const float* __restrict__ w2, const float* __restrict__ b2,
                 float* __restrict__ out, int Brows) {
    extern __shared__ float sm[];
    const int tid  = threadIdx.x;
    const int wid  = tid >> 5;
    const int lane = tid & 31;
    const int tg   = lane >> 2;          // 0..7
    const int tk   = lane & 3;           // 0..3
    const int mw   = (wid >> 1) * 32;    // 4 warps in M
    const int nw   = (wid & 1) * 64;     // 2 warps in N
    const int m0   = blockIdx.x * MT;

    for (int i = tid; i < 1280; i += THREADS) sm[OF_W2 + i] = w2[i];
    if (tid < 128) sm[OF_B1 + tid] = b1[tid];
    if (tid < 10)  sm[OF_B2 + tid] = b2[tid];

    const uint32_t pipe_sm = smem_u32(sm + OF_PIPE);

    // ---- producer addressing ----
    // A/B piece: row = tid>>2 (0..63) plus +64 for second piece; q = tid&3 -> halves [8q, 8q+7]
    const int prow = tid >> 2, pq = tid & 3;
    int msrc = m0 + prow; if (msrc >= Brows) msrc = Brows - 1;
    const float* xsrc = x + (size_t)msrc * KDIM + pq * 8;        // + c*KCH
    const __half* wsrc = g_Wt16 + (size_t)prow * KPAD + pq * 8;  // + c*KCH
    const uint32_t a_sts = (uint32_t)(prow * 80 + pq * 16);      // byte off in A region
    const uint32_t b_dst = a_sts;                                 // byte off in B region

    // A register staging: one chunk (2 rows x 8 floats) held in registers
    float4 rAf[4];
    auto ldgA = [&](int c) {
        const int k0 = c * KCH + pq * 8;
        #pragma unroll
        for (int p = 0; p < 2; ++p) {
            const float* s = xsrc + c * KCH + (size_t)p * 64 * KDIM;
            if (k0 < KDIM) {
                rAf[2 * p]     = *(const float4*)(s);
                rAf[2 * p + 1] = *(const float4*)(s + 4);
            } else {
                rAf[2 * p]     = make_float4(0.f, 0.f, 0.f, 0.f);
                rAf[2 * p + 1] = make_float4(0.f, 0.f, 0.f, 0.f);
            }
        }
    };
    auto stsA = [&](int stage) {
        #pragma unroll
        for (int p = 0; p < 2; ++p) {
            uint4 v;
            v.x = pack_f16x2(rAf[2 * p].x,     rAf[2 * p].y);
            v.y = pack_f16x2(rAf[2 * p].z,     rAf[2 * p].w);
            v.z = pack_f16x2(rAf[2 * p + 1].x, rAf[2 * p + 1].y);
            v.w = pack_f16x2(rAf[2 * p + 1].z, rAf[2 * p + 1].w);
            *(uint4*)((char*)sm + (size_t)stage * STAGE_BYTES + a_sts + (size_t)p * 64 * 80) = v;
        }
    };
    auto issueB = [&](int c, int stage) {
        const uint32_t bb = pipe_sm + (uint32_t)stage * STAGE_BYTES + A_BYTES;
        #pragma unroll
        for (int p = 0; p < 2; ++p)
            cp_async16(bb + b_dst + (uint32_t)p * 64 * 80,
                       wsrc + c * KCH + (size_t)p * 64 * KPAD);
    };

    float acc[2][8][4];
    #pragma unroll
    for (int mi = 0; mi < 2; ++mi)
        #pragma unroll
        for (int ni = 0; ni < 8; ++ni)
            #pragma unroll
            for (int e = 0; e < 4; ++e) acc[mi][ni][e] = 0.f;

    // ldmatrix per-lane A address component:
    // lanes 0-15 -> rows mw+0..15 @ k0, lanes 16-31 -> same rows @ k+8 (bytes +16)
    const uint32_t a_lm = (uint32_t)((mw + (lane & 15)) * 80 + ((lane >> 4) << 4));

    // ---- prologue: B chunks 0..2 in flight, A chunk 0 in smem, chunk 1 in regs ----
    ldgA(0);
    issueB(0, 0); cp_commit();
    issueB(1, 1); cp_commit();
    issueB(2, 2); cp_commit();
    stsA(0);
    ldgA(1);

    // ---- mainloop ----
    for (int c = 0; c < NCHUNK; ++c) {
        const int s = c & (NSTAGES - 1);
        cp_wait2();            // chunk c's B group complete (c+1, c+2 still pending)
        __syncthreads();       // all stsA(c) visible; all reads of stage (c+3)&3's old data done

        if (c + 3 < NCHUNK) issueB(c + 3, (c + 3) & (NSTAGES - 1));   // safe: after barrier
        cp_commit();

        const uint32_t a_base = pipe_sm + (uint32_t)s * STAGE_BYTES + a_lm;
        const uint32_t* Bs32 = (const uint32_t*)((const char*)sm + (size_t)s * STAGE_BYTES + A_BYTES);

        #pragma unroll
        for (int ks = 0; ks < KCH; ks += 16) {
            uint32_t a[2][4];
            #pragma unroll
            for (int mi = 0; mi < 2; ++mi)
                ldmatrix_x4(a[mi], a_base + (uint32_t)(mi * 16 * 80 + ks * 2));
            uint32_t b[8][2];
            #pragma unroll
            for (int ni = 0; ni < 8; ++ni) {
                const uint32_t* bn = Bs32 + (nw + ni * 8 + tg) * (BPITCH / 2) + (ks / 2);
                b[ni][0] = bn[tk];
                b[ni][1] = bn[tk + 4];
            }
            #pragma unroll
            for (int mi = 0; mi < 2; ++mi)
                #pragma unroll
                for (int ni = 0; ni < 8; ++ni)
                    mma_f16(acc[mi][ni], a[mi], b[ni]);
        }

        if (c + 1 < NCHUNK) stsA((c + 1) & (NSTAGES - 1));   // rAf holds chunk c+1
        if (c + 2 < NCHUNK) ldgA(c + 2);
    }

    // ---- epilogue: h = relu(acc + b1) into smem overlay ----
    cp_wait0();
    __syncthreads();
    {
        float* h = sm + OF_PIPE;   // [128][PH]
        #pragma unroll
        for (int mi = 0; mi < 2; ++mi) {
            #pragma unroll
            for (int ni = 0; ni < 8; ++ni) {
                const int r = mw + mi * 16 + tg;
                const int n = nw + ni * 8 + 2 * tk;
                const float bn0 = sm[OF_B1 + n], bn1 = sm[OF_B1 + n + 1];
                h[r * PH + n]           = fmaxf(acc[mi][ni][0] + bn0, 0.f);
                h[r * PH + n + 1]       = fmaxf(acc[mi][ni][1] + bn1, 0.f);
                h[(r + 8) * PH + n]     = fmaxf(acc[mi][ni][2] + bn0, 0.f);
                h[(r + 8) * PH + n + 1] = fmaxf(acc[mi][ni][3] + bn1, 0.f);
            }
        }
    }
    __syncthreads();

    // ---- GEMM2: split-K over 2 threads/row ----
    {
        const float* h = sm + OF_PIPE;
        const int row  = tid & 127;
        const int half = tid >> 7;
        float o[10];
        #pragma unroll
        for (int n = 0; n < 10; ++n) o[n] = 0.f;
        #pragma unroll 8
        for (int k = half * 64; k < half * 64 + 64; ++k) {
            const float t = h[row * PH + k];
            const float* wr = sm + OF_W2 + k * 10;
            #pragma unroll
            for (int n = 0; n < 10; ++n) o[n] = fmaf(t, wr[n], o[n]);
        }
        #pragma unroll
        for (int n = 0; n < 10; ++n) sm[OF_PART + tid * 10 + n] = o[n];
    }
    __syncthreads();
    if (tid < 128) {
        #pragma unroll
        for (int n = 0; n < 10; ++n)
            sm[OF_OUTS + tid * 10 + n] = sm[OF_PART + tid * 10 + n]
                                       + sm[OF_PART + (tid + 128) * 10 + n]
                                       + sm[OF_B2 + n];
    }
    __syncthreads();

    // ---- coalesced store ----
    const int nvalid = (Brows - m0 < MT) ? (Brows - m0) : MT;
    if (nvalid == MT) {
        float4* dst = (float4*)(out + (size_t)m0 * 10);
        const float4* src = (const float4*)(sm + OF_OUTS);
        for (int i = tid; i < MT * 10 / 4; i += THREADS) dst[i] = src[i];
    } else {
        for (int i = tid; i < nvalid * 10; i += THREADS) out[(size_t)m0 * 10 + i] = sm[OF_OUTS + i];
    }
}

// ============================================================================
// Host launch
// ============================================================================
extern "C" void kernel_launch(void* const* d_in, const int* in_sizes, int n_in,
                              void* d_out, int out_size) {
    const float* x      = (const float*)d_in[0];
    const float* conv_w = (const float*)d_in[1];
    const float* w1     = (const float*)d_in[2];
    const float* b1     = (const float*)d_in[3];
    const float* w2     = (const float*)d_in[4];
    const float* b2     = (const float*)d_in[5];
    float* out          = (float*)d_out;
    const int Brows     = in_sizes[0] / KDIM;

    static int configured = 0;
    if (!configured) {
        cudaFuncSetAttribute(fused_mlp_kernel, cudaFuncAttributeMaxDynamicSharedMemorySize, SMEM_BYTES);
        configured = 1;
    }

    prep_kernel<<<(NT * KPAD + 255) / 256, 256>>>(conv_w, w1);

    const int grid = (Brows + MT - 1) / MT;
    fused_mlp_kernel<<<grid, THREADS, SMEM_BYTES>>>(x, b1, w2, b2, out, Brows);
}